// round 1
// baseline (speedup 1.0000x reference)
#include <cuda_runtime.h>

#define Bc  4
#define Nc  2048
#define INC 128
#define Hc  4
#define Dc  64
#define BHc (Bc*Hc)
#define NW  (Nc/32)     // 64 mask words per row

// ---- scratch (no allocations allowed) ----
__device__ float    g_h [BHc*Nc*Dc];   // [bh][n][d]  8 MB
__device__ float    g_u [BHc*Nc];
__device__ float    g_v [BHc*Nc];
__device__ float    g_E1[BHc*Nc];      // exp(v)
__device__ float    g_E2[BHc*Nc];      // exp(0.2 v)
__device__ float    g_F1[BHc*Nc];      // exp(u)
__device__ float    g_F2[BHc*Nc];      // exp(0.2 u)
__device__ unsigned g_maskT[NW*Nc];    // [jword][i]  (transposed for coalesced loads)

// ---- pack adj into transposed bitmask via warp ballot ----
__global__ void k_pack(const int* __restrict__ adj) {
    int idx = blockIdx.x * 256 + threadIdx.x;   // element index into [N,N]
    int i = idx >> 11;          // row
    int j = idx & (Nc - 1);     // col
    int v = adj[idx];
    unsigned bal = __ballot_sync(0xffffffffu, v > 0);
    if ((j & 31) == 0)
        g_maskT[(unsigned)(j >> 5) * Nc + i] = bal;
}

// ---- h = x @ W^T, scattered to [b,h,n,d] ----
__global__ void __launch_bounds__(256) k_lin(const float* __restrict__ x,
                                             const float* __restrict__ W) {
    __shared__ __align__(16) float xt[INC * 64];   // [k][n_local]
    __shared__ __align__(16) float wt[INC * 64];   // [k][o_local]
    int tid = threadIdx.x;
    int o0 = blockIdx.x * 64;       // = head * 64
    int n0 = blockIdx.y * 64;
    int b  = blockIdx.z;

    const float4* xsrc = (const float4*)(x + ((size_t)b * Nc + n0) * INC);
    const float4* wsrc = (const float4*)(W + (size_t)o0 * INC);
#pragma unroll
    for (int q = 0; q < 8; q++) {
        int idx = tid + q * 256;          // float4 index in [64][32]
        int row = idx >> 5;
        int k4  = (idx & 31) << 2;
        float4 xv = xsrc[idx];
        xt[(k4+0)*64+row] = xv.x; xt[(k4+1)*64+row] = xv.y;
        xt[(k4+2)*64+row] = xv.z; xt[(k4+3)*64+row] = xv.w;
        float4 wv = wsrc[idx];
        wt[(k4+0)*64+row] = wv.x; wt[(k4+1)*64+row] = wv.y;
        wt[(k4+2)*64+row] = wv.z; wt[(k4+3)*64+row] = wv.w;
    }
    __syncthreads();

    int tx = tid & 15, ty = tid >> 4;
    float acc[4][4];
#pragma unroll
    for (int r = 0; r < 4; r++)
#pragma unroll
        for (int c = 0; c < 4; c++) acc[r][c] = 0.f;

#pragma unroll 8
    for (int k = 0; k < INC; k++) {
        float4 a = *(const float4*)&xt[k*64 + ty*4];
        float4 bb = *(const float4*)&wt[k*64 + tx*4];
        acc[0][0] += a.x*bb.x; acc[0][1] += a.x*bb.y; acc[0][2] += a.x*bb.z; acc[0][3] += a.x*bb.w;
        acc[1][0] += a.y*bb.x; acc[1][1] += a.y*bb.y; acc[1][2] += a.y*bb.z; acc[1][3] += a.y*bb.w;
        acc[2][0] += a.z*bb.x; acc[2][1] += a.z*bb.y; acc[2][2] += a.z*bb.z; acc[2][3] += a.z*bb.w;
        acc[3][0] += a.w*bb.x; acc[3][1] += a.w*bb.y; acc[3][2] += a.w*bb.z; acc[3][3] += a.w*bb.w;
    }

    int head = blockIdx.x;   // 64-wide col tiles align with heads
    float* dst = g_h + (((size_t)(b*Hc + head)) * Nc + n0) * Dc;
#pragma unroll
    for (int r = 0; r < 4; r++) {
        float4 v = make_float4(acc[r][0], acc[r][1], acc[r][2], acc[r][3]);
        *(float4*)&dst[(ty*4 + r) * Dc + tx*4] = v;
    }
}

// ---- per-node attention logits + factored exponentials ----
__global__ void k_sc(const float* __restrict__ att_src,
                     const float* __restrict__ att_dst) {
    int idx = blockIdx.x * 256 + threadIdx.x;   // [bh*N)
    int bh = idx >> 11;
    int hh = bh & (Hc - 1);
    const float* hp = g_h + (size_t)idx * Dc;
    const float* as = att_src + hh * Dc;
    const float* ad = att_dst + hh * Dc;
    float u = 0.f, v = 0.f;
#pragma unroll
    for (int d = 0; d < Dc; d += 4) {
        float4 hv = *(const float4*)(hp + d);
        float4 a1 = *(const float4*)(as + d);
        float4 a2 = *(const float4*)(ad + d);
        u += hv.x*a1.x + hv.y*a1.y + hv.z*a1.z + hv.w*a1.w;
        v += hv.x*a2.x + hv.y*a2.y + hv.z*a2.z + hv.w*a2.w;
    }
    g_u[idx] = u;  g_v[idx] = v;
    g_F1[idx] = expf(u);        g_F2[idx] = expf(0.2f * u);
    g_E1[idx] = expf(v);        g_E2[idx] = expf(0.2f * v);
}

// ---- main sweep: out_i = (1/Z_i) * sum_j w_ij h_j, w computed on the fly ----
__global__ void __launch_bounds__(128) k_attn(float* __restrict__ out) {
    int bh = blockIdx.y;
    int i0 = blockIdx.x * 128;
    int tid = threadIdx.x;
    int tc = tid & 3;        // 4 col-threads * 16 cols = 64
    int tr = tid >> 2;       // 32 row-threads * 4 rows = 128

    __shared__ __align__(16) float sh[32 * 64];
    __shared__ float sE1[32], sE2[32], sV[32];
    __shared__ unsigned smask[128];

    float acc[4][16];
#pragma unroll
    for (int r = 0; r < 4; r++)
#pragma unroll
        for (int c = 0; c < 16; c++) acc[r][c] = 0.f;
    float Z[4] = {0.f, 0.f, 0.f, 0.f};

    float u[4], F1[4], F2[4];
    int ibase = bh * Nc + i0 + tr * 4;
#pragma unroll
    for (int r = 0; r < 4; r++) {
        u[r]  = g_u[ibase + r];
        F1[r] = g_F1[ibase + r];
        F2[r] = g_F2[ibase + r];
    }

    const float4* ghb = (const float4*)(g_h + (size_t)bh * Nc * Dc);
    int eb = bh * Nc;

    for (int jc = 0; jc < NW; jc++) {
        float4* dsh = (float4*)sh;
#pragma unroll
        for (int q = 0; q < 4; q++)
            dsh[tid + q * 128] = ghb[jc * 512 + tid + q * 128];
        if (tid < 32) {
            sE1[tid] = g_E1[eb + jc * 32 + tid];
            sE2[tid] = g_E2[eb + jc * 32 + tid];
            sV[tid]  = g_v [eb + jc * 32 + tid];
        }
        smask[tid] = g_maskT[(size_t)jc * Nc + i0 + tid];
        __syncthreads();

        unsigned m[4];
#pragma unroll
        for (int r = 0; r < 4; r++) m[r] = smask[tr * 4 + r];

#pragma unroll 8
        for (int jj = 0; jj < 32; jj++) {
            float e1 = sE1[jj];
            float e2 = sE2[jj];
            float nv = -sV[jj];
            unsigned bit = 1u << jj;
            const float* hrow = &sh[jj * 64 + tc * 16];
            float4 h0 = *(const float4*)(hrow + 0);
            float4 h1 = *(const float4*)(hrow + 4);
            float4 h2 = *(const float4*)(hrow + 8);
            float4 h3 = *(const float4*)(hrow + 12);
#pragma unroll
            for (int r = 0; r < 4; r++) {
                float w = (u[r] > nv) ? F1[r] * e1 : F2[r] * e2;
                w = (m[r] & bit) ? w : 0.f;
                Z[r] += w;
                acc[r][0]  += w * h0.x; acc[r][1]  += w * h0.y;
                acc[r][2]  += w * h0.z; acc[r][3]  += w * h0.w;
                acc[r][4]  += w * h1.x; acc[r][5]  += w * h1.y;
                acc[r][6]  += w * h1.z; acc[r][7]  += w * h1.w;
                acc[r][8]  += w * h2.x; acc[r][9]  += w * h2.y;
                acc[r][10] += w * h2.z; acc[r][11] += w * h2.w;
                acc[r][12] += w * h3.x; acc[r][13] += w * h3.y;
                acc[r][14] += w * h3.z; acc[r][15] += w * h3.w;
            }
        }
        __syncthreads();
    }

    int b = bh >> 2, hh = bh & 3;
#pragma unroll
    for (int r = 0; r < 4; r++) {
        float inv = 1.f / Z[r];
        int i = i0 + tr * 4 + r;
        float* dst = out + ((size_t)(b * Nc + i)) * (Hc * Dc) + hh * Dc + tc * 16;
#pragma unroll
        for (int c = 0; c < 16; c++) acc[r][c] *= inv;
        *(float4*)(dst + 0)  = make_float4(acc[r][0],  acc[r][1],  acc[r][2],  acc[r][3]);
        *(float4*)(dst + 4)  = make_float4(acc[r][4],  acc[r][5],  acc[r][6],  acc[r][7]);
        *(float4*)(dst + 8)  = make_float4(acc[r][8],  acc[r][9],  acc[r][10], acc[r][11]);
        *(float4*)(dst + 12) = make_float4(acc[r][12], acc[r][13], acc[r][14], acc[r][15]);
    }
}

extern "C" void kernel_launch(void* const* d_in, const int* in_sizes, int n_in,
                              void* d_out, int out_size) {
    const float* x       = (const float*)d_in[0];
    const int*   adj     = (const int*)  d_in[1];
    const float* W       = (const float*)d_in[2];
    const float* att_src = (const float*)d_in[3];
    const float* att_dst = (const float*)d_in[4];
    float* out = (float*)d_out;

    // pack adjacency bitmask (independent of h)
    k_pack<<<(Nc * Nc) / 256, 256>>>(adj);
    // h = x @ W^T  -> g_h[b,h,n,d]
    k_lin<<<dim3(Hc, Nc / 64, Bc), 256>>>(x, W);
    // logits + factored exps
    k_sc<<<(BHc * Nc) / 256, 256>>>(att_src, att_dst);
    // attention-weighted aggregation
    k_attn<<<dim3(Nc / 128, BHc), 128>>>(out);
}

// round 3
// speedup vs baseline: 3.5638x; 3.5638x over previous
#include <cuda_runtime.h>
#include <cuda_fp16.h>
#include <cstdint>

#define Bc  4
#define Nc  2048
#define INC 128
#define Hc  4
#define Dc  64
#define BHc (Bc*Hc)
#define NW  (Nc/32)

// ---- scratch ----
__device__ float    g_h [BHc*Nc*Dc];   // [bh][n][d] fp32 (for k_sc)
__device__ __half   g_hH[BHc*Nc*Dc];   // [bh][n][d] fp16 (MMA B operand)
__device__ float    g_E1[BHc*Nc];      // exp(v)
__device__ float    g_E2[BHc*Nc];      // exp(0.2 v)
__device__ float    g_F1[BHc*Nc];      // exp(u)
__device__ float    g_F2[BHc*Nc];      // exp(0.2 u)
__device__ unsigned g_maskT[NW*Nc];    // [jword][i]

__device__ __forceinline__ uint32_t smem_u32(const void* p) {
    uint32_t a;
    asm("{ .reg .u64 t; cvta.to.shared.u64 t, %1; cvt.u32.u64 %0, t; }" : "=r"(a) : "l"(p));
    return a;
}

// ---- pack adj into transposed bitmask ----
__global__ void k_pack(const int* __restrict__ adj) {
    int idx = blockIdx.x * 256 + threadIdx.x;
    int i = idx >> 11;
    int j = idx & (Nc - 1);
    int v = adj[idx];
    unsigned bal = __ballot_sync(0xffffffffu, v > 0);
    if ((j & 31) == 0)
        g_maskT[(unsigned)(j >> 5) * Nc + i] = bal;
}

// ---- h = x @ W^T -> g_h fp32 + g_hH fp16, both [bh][n][d] ----
__global__ void __launch_bounds__(256) k_lin(const float* __restrict__ x,
                                             const float* __restrict__ W) {
    __shared__ __align__(16) float xt[INC * 64];
    __shared__ __align__(16) float wt[INC * 64];
    int tid = threadIdx.x;
    int o0 = blockIdx.x * 64;
    int n0 = blockIdx.y * 64;
    int b  = blockIdx.z;

    const float4* xsrc = (const float4*)(x + ((size_t)b * Nc + n0) * INC);
    const float4* wsrc = (const float4*)(W + (size_t)o0 * INC);
#pragma unroll
    for (int q = 0; q < 8; q++) {
        int idx = tid + q * 256;
        int row = idx >> 5;
        int k4  = (idx & 31) << 2;
        float4 xv = xsrc[idx];
        xt[(k4+0)*64+row] = xv.x; xt[(k4+1)*64+row] = xv.y;
        xt[(k4+2)*64+row] = xv.z; xt[(k4+3)*64+row] = xv.w;
        float4 wv = wsrc[idx];
        wt[(k4+0)*64+row] = wv.x; wt[(k4+1)*64+row] = wv.y;
        wt[(k4+2)*64+row] = wv.z; wt[(k4+3)*64+row] = wv.w;
    }
    __syncthreads();

    int tx = tid & 15, ty = tid >> 4;
    float acc[4][4];
#pragma unroll
    for (int r = 0; r < 4; r++)
#pragma unroll
        for (int c = 0; c < 4; c++) acc[r][c] = 0.f;

#pragma unroll 8
    for (int k = 0; k < INC; k++) {
        float4 a  = *(const float4*)&xt[k*64 + ty*4];
        float4 bb = *(const float4*)&wt[k*64 + tx*4];
        acc[0][0] += a.x*bb.x; acc[0][1] += a.x*bb.y; acc[0][2] += a.x*bb.z; acc[0][3] += a.x*bb.w;
        acc[1][0] += a.y*bb.x; acc[1][1] += a.y*bb.y; acc[1][2] += a.y*bb.z; acc[1][3] += a.y*bb.w;
        acc[2][0] += a.z*bb.x; acc[2][1] += a.z*bb.y; acc[2][2] += a.z*bb.z; acc[2][3] += a.z*bb.w;
        acc[3][0] += a.w*bb.x; acc[3][1] += a.w*bb.y; acc[3][2] += a.w*bb.z; acc[3][3] += a.w*bb.w;
    }

    int bh = b * Hc + blockIdx.x;
    float*  dst  = g_h  + (((size_t)bh) * Nc + n0) * Dc;
    __half* dstH = g_hH + (((size_t)bh) * Nc + n0) * Dc;
#pragma unroll
    for (int r = 0; r < 4; r++) {
        *(float4*)&dst[(ty*4 + r) * Dc + tx*4] =
            make_float4(acc[r][0], acc[r][1], acc[r][2], acc[r][3]);
        __half2 p0 = __floats2half2_rn(acc[r][0], acc[r][1]);
        __half2 p1 = __floats2half2_rn(acc[r][2], acc[r][3]);
        uint2 pk;
        pk.x = *(uint32_t*)&p0; pk.y = *(uint32_t*)&p1;
        *(uint2*)&dstH[(ty*4 + r) * Dc + tx*4] = pk;
    }
}

// ---- per-node logits + factored exponentials ----
__global__ void k_sc(const float* __restrict__ att_src,
                     const float* __restrict__ att_dst) {
    int idx = blockIdx.x * 256 + threadIdx.x;
    int bh = idx >> 11;
    int hh = bh & (Hc - 1);
    const float* hp = g_h + (size_t)idx * Dc;
    const float* as = att_src + hh * Dc;
    const float* ad = att_dst + hh * Dc;
    float u = 0.f, v = 0.f;
#pragma unroll
    for (int d = 0; d < Dc; d += 4) {
        float4 hv = *(const float4*)(hp + d);
        float4 a1 = *(const float4*)(as + d);
        float4 a2 = *(const float4*)(ad + d);
        u += hv.x*a1.x + hv.y*a1.y + hv.z*a1.z + hv.w*a1.w;
        v += hv.x*a2.x + hv.y*a2.y + hv.z*a2.z + hv.w*a2.w;
    }
    g_F1[idx] = expf(u);        g_F2[idx] = expf(0.2f * u);
    g_E1[idx] = expf(v);        g_E2[idx] = expf(0.2f * v);
}

// ---- flash-GAT on mma.sync m16n8k16 (f16 in, f32 acc) ----
// CTA: 128 i-rows x 64 d.  8 warps, each owns 16 rows.  Loop j in chunks of 128.
__global__ void __launch_bounds__(256) k_attn(float* __restrict__ out) {
    __shared__ __align__(16) char sH[128 * 128];   // h tile fp16 [j][d], XOR-swizzled
    __shared__ float sE1[128], sE2[128];
    __shared__ unsigned smk[4 * 128];              // [jword within chunk][i-row]

    int tid = threadIdx.x;
    int w   = tid >> 5;
    int lane = tid & 31;
    int g = lane >> 2, t = lane & 3;
    int bh = blockIdx.y;
    int i0 = blockIdx.x * 128;
    int r0 = w * 16 + g;          // local row (strip-relative rows r0, r0+8)
    int r1 = r0 + 8;

    const uint32_t sHb = smem_u32(sH);
    const int eb = bh * Nc;

    float F1a = g_F1[eb + i0 + r0], F2a = g_F2[eb + i0 + r0];
    float F1b = g_F1[eb + i0 + r1], F2b = g_F2[eb + i0 + r1];
    float Z0 = 0.f, Z1 = 0.f;

    float c[8][4];
#pragma unroll
    for (int n = 0; n < 8; n++)
#pragma unroll
        for (int q = 0; q < 4; q++) c[n][q] = 0.f;

    const uint4* hsrc = (const uint4*)(g_hH + (size_t)eb * Dc);

    for (int ch = 0; ch < 16; ch++) {
        __syncthreads();
        int j0 = ch * 128;
        // stage h tile (128 rows x 128B) swizzled
#pragma unroll
        for (int q = 0; q < 4; q++) {
            int idx = tid + q * 256;        // uint4 id: row=idx>>3, chunk=idx&7
            int row = idx >> 3, cc = idx & 7;
            uint4 v = hsrc[(size_t)(j0 + row) * 8 + cc];
            *(uint4*)&sH[row * 128 + ((cc * 16) ^ ((row & 7) * 16))] = v;
        }
        if (tid < 128) sE1[tid] = g_E1[eb + j0 + tid];
        else           sE2[tid - 128] = g_E2[eb + j0 + tid - 128];
        {
            int idx = tid;  // 512 words over 2 iters
            smk[idx]       = g_maskT[(size_t)(ch * 4 + (idx >> 7)) * Nc + i0 + (idx & 127)];
            idx += 256;
            smk[idx]       = g_maskT[(size_t)(ch * 4 + (idx >> 7)) * Nc + i0 + (idx & 127)];
        }
        __syncthreads();

        unsigned mwa[4], mwb[4];
#pragma unroll
        for (int q = 0; q < 4; q++) {
            mwa[q] = smk[q * 128 + r0];
            mwb[q] = smk[q * 128 + r1];
        }

#pragma unroll
        for (int s = 0; s < 8; s++) {
            int jb = s * 16;
            unsigned bsh = (unsigned)((s & 1) * 16 + 2 * t);
            unsigned m0 = mwa[s >> 1] >> bsh;
            unsigned m1 = mwb[s >> 1] >> bsh;
            float2 e1a = *(const float2*)&sE1[jb + 2*t];
            float2 e1b = *(const float2*)&sE1[jb + 2*t + 8];
            float2 e2a = *(const float2*)&sE2[jb + 2*t];
            float2 e2b = *(const float2*)&sE2[jb + 2*t + 8];

            float w00 = (m0 & 1u)   ? fmaxf(F1a*e1a.x, F2a*e2a.x) : 0.f;
            float w01 = (m0 & 2u)   ? fmaxf(F1a*e1a.y, F2a*e2a.y) : 0.f;
            float w08 = (m0 & 256u) ? fmaxf(F1a*e1b.x, F2a*e2b.x) : 0.f;
            float w09 = (m0 & 512u) ? fmaxf(F1a*e1b.y, F2a*e2b.y) : 0.f;
            float w10 = (m1 & 1u)   ? fmaxf(F1b*e1a.x, F2b*e2a.x) : 0.f;
            float w11 = (m1 & 2u)   ? fmaxf(F1b*e1a.y, F2b*e2a.y) : 0.f;
            float w18 = (m1 & 256u) ? fmaxf(F1b*e1b.x, F2b*e2b.x) : 0.f;
            float w19 = (m1 & 512u) ? fmaxf(F1b*e1b.y, F2b*e2b.y) : 0.f;
            Z0 += (w00 + w01) + (w08 + w09);
            Z1 += (w10 + w11) + (w18 + w19);

            __half2 ha0 = __floats2half2_rn(w00, w01);
            __half2 ha1 = __floats2half2_rn(w10, w11);
            __half2 ha2 = __floats2half2_rn(w08, w09);
            __half2 ha3 = __floats2half2_rn(w18, w19);
            uint32_t a0 = *(uint32_t*)&ha0, a1 = *(uint32_t*)&ha1;
            uint32_t a2 = *(uint32_t*)&ha2, a3 = *(uint32_t*)&ha3;

            // B fragments: 4 x ldmatrix.x4.trans, each covers 2 n-tiles
            int mrow = jb + (lane & 15);
            uint32_t rbase = sHb + (uint32_t)mrow * 128;
            uint32_t swz = (uint32_t)((mrow & 7) * 16);
            uint32_t hi  = (uint32_t)((lane >> 4) * 16);
#pragma unroll
            for (int p = 0; p < 4; p++) {
                uint32_t addr = rbase + (((uint32_t)(p * 32) + hi) ^ swz);
                uint32_t b0, b1, b2, b3;
                asm volatile("ldmatrix.sync.aligned.m8n8.x4.trans.shared.b16 {%0,%1,%2,%3}, [%4];"
                             : "=r"(b0), "=r"(b1), "=r"(b2), "=r"(b3) : "r"(addr));
                asm volatile("mma.sync.aligned.m16n8k16.row.col.f32.f16.f16.f32 "
                             "{%0,%1,%2,%3}, {%4,%5,%6,%7}, {%8,%9}, {%0,%1,%2,%3};"
                             : "+f"(c[2*p][0]), "+f"(c[2*p][1]), "+f"(c[2*p][2]), "+f"(c[2*p][3])
                             : "r"(a0), "r"(a1), "r"(a2), "r"(a3), "r"(b0), "r"(b1));
                asm volatile("mma.sync.aligned.m16n8k16.row.col.f32.f16.f16.f32 "
                             "{%0,%1,%2,%3}, {%4,%5,%6,%7}, {%8,%9}, {%0,%1,%2,%3};"
                             : "+f"(c[2*p+1][0]), "+f"(c[2*p+1][1]), "+f"(c[2*p+1][2]), "+f"(c[2*p+1][3])
                             : "r"(a0), "r"(a1), "r"(a2), "r"(a3), "r"(b2), "r"(b3));
            }
        }
    }

    // Z reduce within quad (lanes t=0..3 hold disjoint j-subsets of same rows)
    Z0 += __shfl_xor_sync(0xffffffffu, Z0, 1);
    Z0 += __shfl_xor_sync(0xffffffffu, Z0, 2);
    Z1 += __shfl_xor_sync(0xffffffffu, Z1, 1);
    Z1 += __shfl_xor_sync(0xffffffffu, Z1, 2);
    float inv0 = 1.f / Z0, inv1 = 1.f / Z1;

    int b = bh >> 2, hd = bh & 3;
    float* d0 = out + ((size_t)(b * Nc) + i0 + r0) * (Hc * Dc) + hd * Dc + 2 * t;
    float* d1 = d0 + 8 * (Hc * Dc);
#pragma unroll
    for (int n = 0; n < 8; n++) {
        *(float2*)(d0 + n * 8) = make_float2(c[n][0] * inv0, c[n][1] * inv0);
        *(float2*)(d1 + n * 8) = make_float2(c[n][2] * inv1, c[n][3] * inv1);
    }
}

extern "C" void kernel_launch(void* const* d_in, const int* in_sizes, int n_in,
                              void* d_out, int out_size) {
    const float* x       = (const float*)d_in[0];
    const int*   adj     = (const int*)  d_in[1];
    const float* W       = (const float*)d_in[2];
    const float* att_src = (const float*)d_in[3];
    const float* att_dst = (const float*)d_in[4];
    float* out = (float*)d_out;

    k_pack<<<(Nc * Nc) / 256, 256>>>(adj);
    k_lin<<<dim3(Hc, Nc / 64, Bc), 256>>>(x, W);
    k_sc<<<(BHc * Nc) / 256, 256>>>(att_src, att_dst);
    k_attn<<<dim3(Nc / 128, BHc), 256>>>(out);
}

// round 4
// speedup vs baseline: 6.1311x; 1.7204x over previous
#include <cuda_runtime.h>
#include <cuda_fp16.h>
#include <cstdint>

#define Bc  4
#define Nc  2048
#define INC 128
#define Hc  4
#define Dc  64
#define BHc (Bc*Hc)
#define NW  (Nc/32)

// ---- scratch ----
__device__ __half   g_xH[Bc*Nc*INC];   // x fp16
__device__ __half   g_WH[256*INC];     // W fp16
__device__ __half   g_hH[BHc*Nc*Dc];   // h fp16 [bh][n][d]
__device__ __half   g_E1h[BHc*Nc];     // exp(v)
__device__ __half   g_E2h[BHc*Nc];     // exp(0.2 v)
__device__ __half   g_F1h[BHc*Nc];     // exp(u)
__device__ __half   g_F2h[BHc*Nc];     // exp(0.2 u)
__device__ unsigned g_maskT[NW*Nc];    // [jword][i]

__device__ __forceinline__ uint32_t smem_u32(const void* p) {
    uint32_t a;
    asm("{ .reg .u64 t; cvta.to.shared.u64 t, %1; cvt.u32.u64 %0, t; }" : "=r"(a) : "l"(p));
    return a;
}
__device__ __forceinline__ uint32_t h2u(__half2 h) { return *(uint32_t*)&h; }

// ---- fp32 -> fp16 conversion for x and W ----
__global__ void k_cvt(const float* __restrict__ x, const float* __restrict__ W) {
    int gid = blockIdx.x * 256 + threadIdx.x;       // 262144 float4 of x
    float4 v = ((const float4*)x)[gid];
    uint2 pk;
    __half2 p0 = __floats2half2_rn(v.x, v.y), p1 = __floats2half2_rn(v.z, v.w);
    pk.x = h2u(p0); pk.y = h2u(p1);
    ((uint2*)g_xH)[gid] = pk;
    if (gid < 8192) {                               // 8192 float4 of W
        float4 wv = ((const float4*)W)[gid];
        uint2 qk;
        __half2 q0 = __floats2half2_rn(wv.x, wv.y), q1 = __floats2half2_rn(wv.z, wv.w);
        qk.x = h2u(q0); qk.y = h2u(q1);
        ((uint2*)g_WH)[gid] = qk;
    }
}

// ---- pack adj into transposed bitmask ----
__global__ void k_pack(const int* __restrict__ adj) {
    int idx = blockIdx.x * 256 + threadIdx.x;
    int i = idx >> 11;
    int j = idx & (Nc - 1);
    int v = adj[idx];
    unsigned bal = __ballot_sync(0xffffffffu, v > 0);
    if ((j & 31) == 0)
        g_maskT[(unsigned)(j >> 5) * Nc + i] = bal;
}

// ---- HMMA linear: h = x @ W^T (fp16 in, fp32 acc) with fused u/v/exp epilogue ----
// CTA: 64 n-rows x 128 out-cols (one col-group = 2 heads). 4 warps, warp = 16 rows.
__global__ void __launch_bounds__(128) k_lin_h(const float* __restrict__ att_src,
                                               const float* __restrict__ att_dst) {
    __shared__ __align__(16) char sX[64 * 256];    // 64 rows x 128 halves, swizzled
    __shared__ __align__(16) char sW[128 * 256];   // 128 rows x 128 halves, swizzled
    int tid = threadIdx.x, w = tid >> 5, lane = tid & 31;
    int g = lane >> 2, t = lane & 3;
    int n0 = blockIdx.x * 64, cgrp = blockIdx.y, b = blockIdx.z;

    const uint4* xs = (const uint4*)(g_xH + ((size_t)b * Nc + n0) * INC);
#pragma unroll
    for (int q = 0; q < 8; q++) {
        int idx = tid + q * 128;
        int row = idx >> 4, cc = idx & 15;
        *(uint4*)&sX[row * 256 + ((cc * 16) ^ ((row & 7) * 16))] = xs[idx];
    }
    const uint4* ws = (const uint4*)(g_WH + (size_t)cgrp * 128 * INC);
#pragma unroll
    for (int q = 0; q < 16; q++) {
        int idx = tid + q * 128;
        int row = idx >> 4, cc = idx & 15;
        *(uint4*)&sW[row * 256 + ((cc * 16) ^ ((row & 7) * 16))] = ws[idx];
    }
    __syncthreads();

    float c[16][4];
#pragma unroll
    for (int n = 0; n < 16; n++)
#pragma unroll
        for (int q = 0; q < 4; q++) c[n][q] = 0.f;

    uint32_t sXb = smem_u32(sX), sWb = smem_u32(sW);
    int arow = w * 16 + (lane & 15);
    uint32_t abase = sXb + (uint32_t)arow * 256;
    uint32_t hi16  = (uint32_t)(lane >> 4) * 16;
    uint32_t aswz  = (uint32_t)((arow & 7) * 16);
    // B (W) non-trans x4: rows o = p*16 + (lane&7) + (lane>=16)*8, kbyte + ((lane>>3)&1)*16
    int brow_base = (lane & 7) + ((lane >> 4) << 3);
    uint32_t bk16 = (uint32_t)(((lane >> 3) & 1) * 16);

#pragma unroll
    for (int ks = 0; ks < 8; ks++) {
        uint32_t a0, a1, a2, a3;
        uint32_t aaddr = abase + (((uint32_t)(ks * 32) + hi16) ^ aswz);
        asm volatile("ldmatrix.sync.aligned.m8n8.x4.shared.b16 {%0,%1,%2,%3}, [%4];"
                     : "=r"(a0), "=r"(a1), "=r"(a2), "=r"(a3) : "r"(aaddr));
#pragma unroll
        for (int p = 0; p < 8; p++) {
            int brow = p * 16 + brow_base;
            uint32_t baddr = sWb + (uint32_t)brow * 256 +
                             (((uint32_t)(ks * 32) + bk16) ^ ((uint32_t)((brow & 7) * 16)));
            uint32_t b0, b1, b2, b3;
            asm volatile("ldmatrix.sync.aligned.m8n8.x4.shared.b16 {%0,%1,%2,%3}, [%4];"
                         : "=r"(b0), "=r"(b1), "=r"(b2), "=r"(b3) : "r"(baddr));
            asm volatile("mma.sync.aligned.m16n8k16.row.col.f32.f16.f16.f32 "
                         "{%0,%1,%2,%3}, {%4,%5,%6,%7}, {%8,%9}, {%0,%1,%2,%3};"
                         : "+f"(c[2*p][0]), "+f"(c[2*p][1]), "+f"(c[2*p][2]), "+f"(c[2*p][3])
                         : "r"(a0), "r"(a1), "r"(a2), "r"(a3), "r"(b0), "r"(b1));
            asm volatile("mma.sync.aligned.m16n8k16.row.col.f32.f16.f16.f32 "
                         "{%0,%1,%2,%3}, {%4,%5,%6,%7}, {%8,%9}, {%0,%1,%2,%3};"
                         : "+f"(c[2*p+1][0]), "+f"(c[2*p+1][1]), "+f"(c[2*p+1][2]), "+f"(c[2*p+1][3])
                         : "r"(a0), "r"(a1), "r"(a2), "r"(a3), "r"(b2), "r"(b3));
        }
    }

    // epilogue: store h fp16 + per-row (u,v) partials
    float up[2][2] = {{0.f,0.f},{0.f,0.f}}, vp[2][2] = {{0.f,0.f},{0.f,0.f}};
    int row0 = w * 16 + g;
#pragma unroll
    for (int n = 0; n < 16; n++) {
        int hl = n >> 3;
        int head = cgrp * 2 + hl;
        int d = (n & 7) * 8 + 2 * t;
        float2 as2 = __ldg((const float2*)(att_src + head * 64 + d));
        float2 ad2 = __ldg((const float2*)(att_dst + head * 64 + d));
        up[0][hl] += c[n][0]*as2.x + c[n][1]*as2.y;
        vp[0][hl] += c[n][0]*ad2.x + c[n][1]*ad2.y;
        up[1][hl] += c[n][2]*as2.x + c[n][3]*as2.y;
        vp[1][hl] += c[n][2]*ad2.x + c[n][3]*ad2.y;
        __half2 h0 = __floats2half2_rn(c[n][0], c[n][1]);
        __half2 h1 = __floats2half2_rn(c[n][2], c[n][3]);
        size_t base = ((size_t)(b * Hc + head) * Nc + n0 + row0) * Dc + d;
        *(uint32_t*)&g_hH[base]          = h2u(h0);
        *(uint32_t*)&g_hH[base + 8 * Dc] = h2u(h1);
    }
#pragma unroll
    for (int rh = 0; rh < 2; rh++)
#pragma unroll
        for (int hl = 0; hl < 2; hl++) {
            up[rh][hl] += __shfl_xor_sync(0xffffffffu, up[rh][hl], 1);
            up[rh][hl] += __shfl_xor_sync(0xffffffffu, up[rh][hl], 2);
            vp[rh][hl] += __shfl_xor_sync(0xffffffffu, vp[rh][hl], 1);
            vp[rh][hl] += __shfl_xor_sync(0xffffffffu, vp[rh][hl], 2);
        }
    if (t == 0) {
#pragma unroll
        for (int rh = 0; rh < 2; rh++)
#pragma unroll
            for (int hl = 0; hl < 2; hl++) {
                int head = cgrp * 2 + hl;
                int idx = (b * Hc + head) * Nc + n0 + row0 + rh * 8;
                float u = up[rh][hl], v = vp[rh][hl];
                g_F1h[idx] = __float2half_rn(expf(u));
                g_F2h[idx] = __float2half_rn(expf(0.2f * u));
                g_E1h[idx] = __float2half_rn(expf(v));
                g_E2h[idx] = __float2half_rn(expf(0.2f * v));
            }
    }
}

// ---- flash-GAT: half2 P-gen, mask via AND, Z via ones-MMA ----
__global__ void __launch_bounds__(256) k_attn(float* __restrict__ out) {
    __shared__ __align__(16) char sH[128 * 128];   // h tile fp16 [j][d], XOR-swizzled
    __shared__ __align__(4) __half sE1h[128], sE2h[128];
    __shared__ unsigned smk[4 * 128];

    int tid = threadIdx.x;
    int w = tid >> 5, lane = tid & 31;
    int g = lane >> 2, t = lane & 3;
    int bh = blockIdx.y;
    int i0 = blockIdx.x * 128;
    int r0 = w * 16 + g;
    int r1 = r0 + 8;
    const uint32_t sHb = smem_u32(sH);
    const int eb = bh * Nc;

    __half2 F1a2 = __half2half2(g_F1h[eb + i0 + r0]);
    __half2 F2a2 = __half2half2(g_F2h[eb + i0 + r0]);
    __half2 F1b2 = __half2half2(g_F1h[eb + i0 + r1]);
    __half2 F2b2 = __half2half2(g_F2h[eb + i0 + r1]);

    float c[8][4];
#pragma unroll
    for (int n = 0; n < 8; n++)
#pragma unroll
        for (int q = 0; q < 4; q++) c[n][q] = 0.f;
    float cz[4] = {0.f, 0.f, 0.f, 0.f};

    const uint4* hsrc = (const uint4*)(g_hH + (size_t)eb * Dc);
    const __half2* sE1h2 = (const __half2*)sE1h;
    const __half2* sE2h2 = (const __half2*)sE2h;
    const uint32_t ONES = 0x3C003C00u;
    int tb = 2 * t;

    for (int ch = 0; ch < 16; ch++) {
        __syncthreads();
        int j0 = ch * 128;
#pragma unroll
        for (int q = 0; q < 4; q++) {
            int idx = tid + q * 256;
            int row = idx >> 3, cc = idx & 7;
            uint4 v = hsrc[(size_t)(j0 + row) * 8 + cc];
            *(uint4*)&sH[row * 128 + ((cc * 16) ^ ((row & 7) * 16))] = v;
        }
        if (tid < 64)        ((uint32_t*)sE1h)[tid]      = ((const uint32_t*)(g_E1h + eb + j0))[tid];
        else if (tid < 128)  ((uint32_t*)sE2h)[tid - 64] = ((const uint32_t*)(g_E2h + eb + j0))[tid - 64];
        {
            int idx = tid;
            smk[idx] = g_maskT[(size_t)(ch * 4 + (idx >> 7)) * Nc + i0 + (idx & 127)];
            idx += 256;
            smk[idx] = g_maskT[(size_t)(ch * 4 + (idx >> 7)) * Nc + i0 + (idx & 127)];
        }
        __syncthreads();

        unsigned mwa[4], mwb[4];
#pragma unroll
        for (int q = 0; q < 4; q++) {
            mwa[q] = smk[q * 128 + r0];
            mwb[q] = smk[q * 128 + r1];
        }

#pragma unroll
        for (int s = 0; s < 8; s++) {
            uint32_t m0 = mwa[s >> 1] >> ((s & 1) * 16);
            uint32_t m1 = mwb[s >> 1] >> ((s & 1) * 16);
            __half2 e1lo = sE1h2[s * 8 + t],     e1hi = sE1h2[s * 8 + 4 + t];
            __half2 e2lo = sE2h2[s * 8 + t],     e2hi = sE2h2[s * 8 + 4 + t];

            uint32_t wl0 = h2u(__hmax2(__hmul2(F1a2, e1lo), __hmul2(F2a2, e2lo)));
            uint32_t wl1 = h2u(__hmax2(__hmul2(F1b2, e1lo), __hmul2(F2b2, e2lo)));
            uint32_t wh0 = h2u(__hmax2(__hmul2(F1a2, e1hi), __hmul2(F2a2, e2hi)));
            uint32_t wh1 = h2u(__hmax2(__hmul2(F1b2, e1hi), __hmul2(F2b2, e2hi)));

            uint32_t bl0 = (m0 >> tb) & 3u,       bl1 = (m1 >> tb) & 3u;
            uint32_t bh0 = (m0 >> (tb + 8)) & 3u, bh1 = (m1 >> (tb + 8)) & 3u;
            uint32_t a0 = wl0 & (((bl0 & 1u) * 0xFFFFu) | ((bl0 >> 1) * 0xFFFF0000u));
            uint32_t a1 = wl1 & (((bl1 & 1u) * 0xFFFFu) | ((bl1 >> 1) * 0xFFFF0000u));
            uint32_t a2 = wh0 & (((bh0 & 1u) * 0xFFFFu) | ((bh0 >> 1) * 0xFFFF0000u));
            uint32_t a3 = wh1 & (((bh1 & 1u) * 0xFFFFu) | ((bh1 >> 1) * 0xFFFF0000u));

            // Z row-sums via ones-B MMA
            asm volatile("mma.sync.aligned.m16n8k16.row.col.f32.f16.f16.f32 "
                         "{%0,%1,%2,%3}, {%4,%5,%6,%7}, {%8,%9}, {%0,%1,%2,%3};"
                         : "+f"(cz[0]), "+f"(cz[1]), "+f"(cz[2]), "+f"(cz[3])
                         : "r"(a0), "r"(a1), "r"(a2), "r"(a3), "r"(ONES), "r"(ONES));

            int mrow = s * 16 + (lane & 15);
            uint32_t rbase = sHb + (uint32_t)mrow * 128;
            uint32_t swz = (uint32_t)((mrow & 7) * 16);
            uint32_t hi  = (uint32_t)((lane >> 4) * 16);
#pragma unroll
            for (int p = 0; p < 4; p++) {
                uint32_t addr = rbase + (((uint32_t)(p * 32) + hi) ^ swz);
                uint32_t b0, b1, b2, b3;
                asm volatile("ldmatrix.sync.aligned.m8n8.x4.trans.shared.b16 {%0,%1,%2,%3}, [%4];"
                             : "=r"(b0), "=r"(b1), "=r"(b2), "=r"(b3) : "r"(addr));
                asm volatile("mma.sync.aligned.m16n8k16.row.col.f32.f16.f16.f32 "
                             "{%0,%1,%2,%3}, {%4,%5,%6,%7}, {%8,%9}, {%0,%1,%2,%3};"
                             : "+f"(c[2*p][0]), "+f"(c[2*p][1]), "+f"(c[2*p][2]), "+f"(c[2*p][3])
                             : "r"(a0), "r"(a1), "r"(a2), "r"(a3), "r"(b0), "r"(b1));
                asm volatile("mma.sync.aligned.m16n8k16.row.col.f32.f16.f16.f32 "
                             "{%0,%1,%2,%3}, {%4,%5,%6,%7}, {%8,%9}, {%0,%1,%2,%3};"
                             : "+f"(c[2*p+1][0]), "+f"(c[2*p+1][1]), "+f"(c[2*p+1][2]), "+f"(c[2*p+1][3])
                             : "r"(a0), "r"(a1), "r"(a2), "r"(a3), "r"(b2), "r"(b3));
            }
        }
    }

    float inv0 = 1.f / cz[0];    // all columns of ones-MMA D equal the row sum
    float inv1 = 1.f / cz[2];

    int b = bh >> 2, hd = bh & 3;
    float* d0 = out + ((size_t)(b * Nc) + i0 + r0) * (Hc * Dc) + hd * Dc + 2 * t;
    float* d1 = d0 + 8 * (Hc * Dc);
#pragma unroll
    for (int n = 0; n < 8; n++) {
        *(float2*)(d0 + n * 8) = make_float2(c[n][0] * inv0, c[n][1] * inv0);
        *(float2*)(d1 + n * 8) = make_float2(c[n][2] * inv1, c[n][3] * inv1);
    }
}

extern "C" void kernel_launch(void* const* d_in, const int* in_sizes, int n_in,
                              void* d_out, int out_size) {
    const float* x       = (const float*)d_in[0];
    const int*   adj     = (const int*)  d_in[1];
    const float* W       = (const float*)d_in[2];
    const float* att_src = (const float*)d_in[3];
    const float* att_dst = (const float*)d_in[4];
    float* out = (float*)d_out;

    k_cvt<<<1024, 256>>>(x, W);
    k_pack<<<(Nc * Nc) / 256, 256>>>(adj);
    k_lin_h<<<dim3(Nc / 64, 2, Bc), 128>>>(att_src, att_dst);
    k_attn<<<dim3(Nc / 128, BHc), 256>>>(out);
}